// round 5
// baseline (speedup 1.0000x reference)
#include <cuda_runtime.h>
#include <cuda_bf16.h>

// ROIRotate: bilinear crop-and-resize of axis-aligned boxes from an NHWC
// feature map.
//
// Shapes (static for this problem):
//   feature_map: (8, 128, 128, 32) fp32
//   boxes:       (2048, 9) fp32
//   box_indices: (2048,)  — int64 in the reference, but the harness downcasts
//                 integer inputs to int32 on device. Read as int32.
//   max_width:   64 (scalar; hardcoded)
// Output: crops (2048, 8, 64, 32) fp32, then padded_width (2048,) fp32,
// concatenated flat in d_out.

#define ROI_HEIGHT 8
#define ROI_MAXW   64
#define ROI_NBOX   2048
#define FM_N       8
#define FM_H       128
#define FM_W       128
#define FM_C       32

// threads: one per (box, v, u, channel-quad). quads = FM_C/4 = 8.
// total = 2048 * 8 * 64 * 8 = 8,388,608

__global__ __launch_bounds__(256, 8)
void roi_rotate_kernel(const float* __restrict__ fm,
                       const float* __restrict__ boxes,
                       const int* __restrict__ bidx,
                       float* __restrict__ out)
{
    int gid  = blockIdx.x * blockDim.x + threadIdx.x;
    int quad = gid & 7;          // channel quad 0..7
    int pos  = gid >> 3;         // (b, v, u)
    int u    = pos & (ROI_MAXW - 1);
    int bv   = pos >> 6;
    int v    = bv & (ROI_HEIGHT - 1);
    int b    = bv >> 3;

    // Box params (broadcast loads; boxes array is tiny and cache-hot)
    const float* bp = boxes + b * 9;
    float x1 = bp[0] * 0.25f, y1 = bp[1] * 0.25f;
    float x2 = bp[2] * 0.25f, y2 = bp[3] * 0.25f;
    float x4 = bp[6] * 0.25f, y4 = bp[7] * 0.25f;

    float box_w = x2 - x1;
    float box_h = y4 - y1;
    float width = (float)ROI_HEIGHT * box_w / fmaxf(box_h, 1e-6f);
    width = fminf(fmaxf(width, 1.0f), (float)ROI_MAXW);

    float4 r = make_float4(0.f, 0.f, 0.f, 0.f);

    if ((float)u < width) {
        float tu = (float)u / width;
        float tv = (float)v * (1.0f / ROI_HEIGHT);
        float sx = x1 + tu * (x2 - x1) + tv * (x4 - x1);
        float sy = y1 + tu * (y2 - y1) + tv * (y4 - y1);

        float fx0 = floorf(sx);
        float fy0 = floorf(sy);
        float wx = sx - fx0;
        float wy = sy - fy0;

        int x0i = min(max((int)fx0, 0), FM_W - 1);
        int x1i = min(x0i + 1, FM_W - 1);
        int y0i = min(max((int)fy0, 0), FM_H - 1);
        int y1i = min(y0i + 1, FM_H - 1);

        int n = bidx[b];
        int co = quad << 2;
        const float* row0 = fm + (((size_t)(n * FM_H + y0i) * FM_W) << 5) + co;
        const float* row1 = fm + (((size_t)(n * FM_H + y1i) * FM_W) << 5) + co;

        float4 g00 = *(const float4*)(row0 + ((size_t)x0i << 5));
        float4 g01 = *(const float4*)(row0 + ((size_t)x1i << 5));
        float4 g10 = *(const float4*)(row1 + ((size_t)x0i << 5));
        float4 g11 = *(const float4*)(row1 + ((size_t)x1i << 5));

        float w00 = (1.f - wy) * (1.f - wx);
        float w01 = (1.f - wy) * wx;
        float w10 = wy * (1.f - wx);
        float w11 = wy * wx;

        r.x = w00 * g00.x + w01 * g01.x + w10 * g10.x + w11 * g11.x;
        r.y = w00 * g00.y + w01 * g01.y + w10 * g10.y + w11 * g11.y;
        r.z = w00 * g00.z + w01 * g01.z + w10 * g10.z + w11 * g11.z;
        r.w = w00 * g00.w + w01 * g01.w + w10 * g10.w + w11 * g11.w;
    }

    // Coalesced: consecutive gid -> consecutive 16B chunks
    *(float4*)(out + (((size_t)pos) << 5) + (quad << 2)) = r;

    // padded_width, once per box
    if (u == 0 && v == 0 && quad == 0) {
        out[(size_t)ROI_NBOX * ROI_HEIGHT * ROI_MAXW * FM_C + b] =
            (float)ROI_MAXW - width;
    }
}

extern "C" void kernel_launch(void* const* d_in, const int* in_sizes, int n_in,
                              void* d_out, int out_size)
{
    const float* fm    = (const float*)d_in[0];
    const float* boxes = (const float*)d_in[1];
    const int*   bidx  = (const int*)d_in[2];
    float*       out   = (float*)d_out;

    const int total = ROI_NBOX * ROI_HEIGHT * ROI_MAXW * (FM_C / 4); // 8,388,608
    const int block = 256;
    const int grid  = total / block;                                 // 32768

    roi_rotate_kernel<<<grid, block>>>(fm, boxes, bidx, out);
}

// round 8
// speedup vs baseline: 1.1031x; 1.1031x over previous
#include <cuda_runtime.h>
#include <cuda_bf16.h>

// ROIRotate: bilinear crop-and-resize of axis-aligned boxes from an NHWC
// feature map.
//
// Shapes (static):
//   feature_map: (8, 128, 128, 32) fp32  (~16.7 MB, L2-resident)
//   boxes:       (2048, 9) fp32
//   box_indices: (2048,) int32 (harness downcasts the reference's int64)
//   max_width:   64
// Output: crops (2048, 8, 64, 32) fp32 + padded_width (2048,) fp32, flat.
//
// Two kernels:
//   1. box_prep: per-box math (division, width clip) -> 8-float param block,
//      and writes padded_width to the output tail.
//   2. main: one thread per (box, v, u, channel-quad-pair). Loads params,
//      2 FMAs for sample coords, 8 gathers (LDG.128), 2 stores (STG.128).

#define ROI_HEIGHT 8
#define ROI_MAXW   64
#define ROI_NBOX   2048
#define FM_N       8
#define FM_H       128
#define FM_W       128
#define FM_C       32

// Per-box param block: {x1, y1, du_x, du_y, dv_x, dv_y, width, n_as_float_bits}
__device__ __align__(32) float g_boxparams[ROI_NBOX * 8];

__global__ void box_prep_kernel(const float* __restrict__ boxes,
                                const int* __restrict__ bidx,
                                float* __restrict__ out)
{
    int b = blockIdx.x * blockDim.x + threadIdx.x;
    if (b >= ROI_NBOX) return;

    const float* bp = boxes + b * 9;
    float x1 = bp[0] * 0.25f, y1 = bp[1] * 0.25f;
    float x2 = bp[2] * 0.25f, y2 = bp[3] * 0.25f;
    float x4 = bp[6] * 0.25f, y4 = bp[7] * 0.25f;

    float box_w = x2 - x1;
    float box_h = y4 - y1;
    float width = (float)ROI_HEIGHT * box_w / fmaxf(box_h, 1e-6f);
    width = fminf(fmaxf(width, 1.0f), (float)ROI_MAXW);
    float inv_w = 1.0f / width;

    float* p = g_boxparams + b * 8;
    float4 p0 = make_float4(x1, y1, (x2 - x1) * inv_w, (y2 - y1) * inv_w);
    float4 p1 = make_float4((x4 - x1) * (1.0f / ROI_HEIGHT),
                            (y4 - y1) * (1.0f / ROI_HEIGHT),
                            width,
                            __int_as_float(bidx[b]));
    *(float4*)(p)     = p0;
    *(float4*)(p + 4) = p1;

    out[(size_t)ROI_NBOX * ROI_HEIGHT * ROI_MAXW * FM_C + b] =
        (float)ROI_MAXW - width;
}

// threads: one per (box, v, u, quad-pair). pairs = FM_C/8 = 4.
// total = 2048 * 8 * 64 * 4 = 4,194,304
__global__ __launch_bounds__(256)
void roi_rotate_kernel(const float* __restrict__ fm,
                       float* __restrict__ out)
{
    int gid  = blockIdx.x * blockDim.x + threadIdx.x;
    int half = gid & 3;          // quad-pair 0..3 (8 channels each)
    int pos  = gid >> 2;         // (b, v, u)
    int u    = pos & (ROI_MAXW - 1);
    int bv   = pos >> 6;
    int v    = bv & (ROI_HEIGHT - 1);
    int b    = bv >> 3;

    const float* p = g_boxparams + b * 8;
    float4 p0 = *(const float4*)(p);      // x1, y1, du_x, du_y
    float4 p1 = *(const float4*)(p + 4);  // dv_x, dv_y, width, n bits

    float4 rA = make_float4(0.f, 0.f, 0.f, 0.f);
    float4 rB = make_float4(0.f, 0.f, 0.f, 0.f);

    float uf = (float)u, vf = (float)v;

    if (uf < p1.z) {
        float sx = fmaf(uf, p0.z, fmaf(vf, p1.x, p0.x));
        float sy = fmaf(uf, p0.w, fmaf(vf, p1.y, p0.y));

        float fx0 = floorf(sx);
        float fy0 = floorf(sy);
        float wx = sx - fx0;
        float wy = sy - fy0;

        int x0i = min(max((int)fx0, 0), FM_W - 1);
        int x1i = min(x0i + 1, FM_W - 1);
        int y0i = min(max((int)fy0, 0), FM_H - 1);
        int y1i = min(y0i + 1, FM_H - 1);

        int n  = __float_as_int(p1.w);
        int co = half << 3;  // channel offset (8 floats)
        const float* row0 = fm + (((size_t)(n * FM_H + y0i) * FM_W) << 5) + co;
        const float* row1 = fm + (((size_t)(n * FM_H + y1i) * FM_W) << 5) + co;
        const float* c00 = row0 + ((size_t)x0i << 5);
        const float* c01 = row0 + ((size_t)x1i << 5);
        const float* c10 = row1 + ((size_t)x0i << 5);
        const float* c11 = row1 + ((size_t)x1i << 5);

        float4 a00 = *(const float4*)(c00);
        float4 a01 = *(const float4*)(c01);
        float4 a10 = *(const float4*)(c10);
        float4 a11 = *(const float4*)(c11);
        float4 b00 = *(const float4*)(c00 + 4);
        float4 b01 = *(const float4*)(c01 + 4);
        float4 b10 = *(const float4*)(c10 + 4);
        float4 b11 = *(const float4*)(c11 + 4);

        float w00 = (1.f - wy) * (1.f - wx);
        float w01 = (1.f - wy) * wx;
        float w10 = wy * (1.f - wx);
        float w11 = wy * wx;

        rA.x = fmaf(w00, a00.x, fmaf(w01, a01.x, fmaf(w10, a10.x, w11 * a11.x)));
        rA.y = fmaf(w00, a00.y, fmaf(w01, a01.y, fmaf(w10, a10.y, w11 * a11.y)));
        rA.z = fmaf(w00, a00.z, fmaf(w01, a01.z, fmaf(w10, a10.z, w11 * a11.z)));
        rA.w = fmaf(w00, a00.w, fmaf(w01, a01.w, fmaf(w10, a10.w, w11 * a11.w)));
        rB.x = fmaf(w00, b00.x, fmaf(w01, b01.x, fmaf(w10, b10.x, w11 * b11.x)));
        rB.y = fmaf(w00, b00.y, fmaf(w01, b01.y, fmaf(w10, b10.y, w11 * b11.y)));
        rB.z = fmaf(w00, b00.z, fmaf(w01, b01.z, fmaf(w10, b10.z, w11 * b11.z)));
        rB.w = fmaf(w00, b00.w, fmaf(w01, b01.w, fmaf(w10, b10.w, w11 * b11.w)));
    }

    // Coalesced: consecutive gid -> consecutive 32B chunks
    float* dst = out + (((size_t)pos) << 5) + (half << 3);
    *(float4*)(dst)     = rA;
    *(float4*)(dst + 4) = rB;
}

extern "C" void kernel_launch(void* const* d_in, const int* in_sizes, int n_in,
                              void* d_out, int out_size)
{
    const float* fm    = (const float*)d_in[0];
    const float* boxes = (const float*)d_in[1];
    const int*   bidx  = (const int*)d_in[2];
    float*       out   = (float*)d_out;

    box_prep_kernel<<<ROI_NBOX / 256, 256>>>(boxes, bidx, out);

    const int total = ROI_NBOX * ROI_HEIGHT * ROI_MAXW * (FM_C / 8); // 4,194,304
    roi_rotate_kernel<<<total / 256, 256>>>(fm, out);
}

// round 11
// speedup vs baseline: 1.4901x; 1.3509x over previous
#include <cuda_runtime.h>
#include <cuda_bf16.h>

// ROIRotate: bilinear crop-and-resize of axis-aligned boxes from an NHWC
// feature map.
//
// Shapes (static):
//   feature_map: (8, 128, 128, 32) fp32  (~16.7 MB, L2-resident)
//   boxes:       (2048, 9) fp32
//   box_indices: (2048,) int32 (harness downcasts the reference's int64)
//   max_width:   64
// Output: crops (2048, 8, 64, 32) fp32 + padded_width (2048,) fp32, flat.
//
// Kernel 1 (box_prep): per-box math -> 8-float param block + padded_width.
// Kernel 2 (main): 8 lanes per sample position, 16 B of channels per lane.
//   This makes each bilinear corner ONE LDG.128 instruction per warp that
//   covers complete 128 B channel lines (minimal L1 wavefronts: 4 gather +
//   1 store per position). Output stores use __stcs to keep the feature map
//   resident in L2.

#define ROI_HEIGHT 8
#define ROI_MAXW   64
#define ROI_NBOX   2048
#define FM_N       8
#define FM_H       128
#define FM_W       128
#define FM_C       32

// Per-box param block: {x1, y1, du_x, du_y, dv_x, dv_y, width, n_as_float_bits}
__device__ __align__(32) float g_boxparams[ROI_NBOX * 8];

__global__ void box_prep_kernel(const float* __restrict__ boxes,
                                const int* __restrict__ bidx,
                                float* __restrict__ out)
{
    int b = blockIdx.x * blockDim.x + threadIdx.x;
    if (b >= ROI_NBOX) return;

    const float* bp = boxes + b * 9;
    float x1 = bp[0] * 0.25f, y1 = bp[1] * 0.25f;
    float x2 = bp[2] * 0.25f, y2 = bp[3] * 0.25f;
    float x4 = bp[6] * 0.25f, y4 = bp[7] * 0.25f;

    float box_w = x2 - x1;
    float box_h = y4 - y1;
    float width = (float)ROI_HEIGHT * box_w / fmaxf(box_h, 1e-6f);
    width = fminf(fmaxf(width, 1.0f), (float)ROI_MAXW);
    float inv_w = 1.0f / width;

    float* p = g_boxparams + b * 8;
    float4 p0 = make_float4(x1, y1, (x2 - x1) * inv_w, (y2 - y1) * inv_w);
    float4 p1 = make_float4((x4 - x1) * (1.0f / ROI_HEIGHT),
                            (y4 - y1) * (1.0f / ROI_HEIGHT),
                            width,
                            __int_as_float(bidx[b]));
    *(float4*)(p)     = p0;
    *(float4*)(p + 4) = p1;

    out[(size_t)ROI_NBOX * ROI_HEIGHT * ROI_MAXW * FM_C + b] =
        (float)ROI_MAXW - width;
}

// threads: one per (box, v, u, channel-quad). quads = FM_C/4 = 8.
// total = 2048 * 8 * 64 * 8 = 8,388,608
// A warp covers 4 positions x 8 quads: each corner gather is ONE LDG.128
// instruction touching 4 complete 128B lines -> 4 wavefronts (optimal).
__global__ __launch_bounds__(256)
void roi_rotate_kernel(const float* __restrict__ fm,
                       float* __restrict__ out)
{
    int gid  = blockIdx.x * blockDim.x + threadIdx.x;
    int quad = gid & 7;          // channel quad 0..7 (16 B)
    int pos  = gid >> 3;         // (b, v, u)
    int u    = pos & (ROI_MAXW - 1);
    int bv   = pos >> 6;
    int v    = bv & (ROI_HEIGHT - 1);
    int b    = bv >> 3;

    const float* p = g_boxparams + b * 8;
    float4 p0 = *(const float4*)(p);      // x1, y1, du_x, du_y
    float4 p1 = *(const float4*)(p + 4);  // dv_x, dv_y, width, n bits

    float4 r = make_float4(0.f, 0.f, 0.f, 0.f);

    float uf = (float)u, vf = (float)v;

    if (uf < p1.z) {
        float sx = fmaf(uf, p0.z, fmaf(vf, p1.x, p0.x));
        float sy = fmaf(uf, p0.w, fmaf(vf, p1.y, p0.y));

        float fx0 = floorf(sx);
        float fy0 = floorf(sy);
        float wx = sx - fx0;
        float wy = sy - fy0;

        int x0i = min(max((int)fx0, 0), FM_W - 1);
        int x1i = min(x0i + 1, FM_W - 1);
        int y0i = min(max((int)fy0, 0), FM_H - 1);
        int y1i = min(y0i + 1, FM_H - 1);

        int n  = __float_as_int(p1.w);
        int co = quad << 2;   // 4 floats = 16 B per lane
        const float* row0 = fm + (((size_t)(n * FM_H + y0i) * FM_W) << 5) + co;
        const float* row1 = fm + (((size_t)(n * FM_H + y1i) * FM_W) << 5) + co;

        float4 g00 = *(const float4*)(row0 + ((size_t)x0i << 5));
        float4 g01 = *(const float4*)(row0 + ((size_t)x1i << 5));
        float4 g10 = *(const float4*)(row1 + ((size_t)x0i << 5));
        float4 g11 = *(const float4*)(row1 + ((size_t)x1i << 5));

        float w00 = (1.f - wy) * (1.f - wx);
        float w01 = (1.f - wy) * wx;
        float w10 = wy * (1.f - wx);
        float w11 = wy * wx;

        r.x = fmaf(w00, g00.x, fmaf(w01, g01.x, fmaf(w10, g10.x, w11 * g11.x)));
        r.y = fmaf(w00, g00.y, fmaf(w01, g01.y, fmaf(w10, g10.y, w11 * g11.y)));
        r.z = fmaf(w00, g00.z, fmaf(w01, g01.z, fmaf(w10, g10.z, w11 * g11.z)));
        r.w = fmaf(w00, g00.w, fmaf(w01, g01.w, fmaf(w10, g10.w, w11 * g11.w)));
    }

    // Coalesced streaming store: consecutive gid -> consecutive 16B chunks.
    // __stcs: don't let the 134MB output evict the L2-resident feature map.
    __stcs((float4*)(out + (((size_t)pos) << 5) + (quad << 2)), r);
}

extern "C" void kernel_launch(void* const* d_in, const int* in_sizes, int n_in,
                              void* d_out, int out_size)
{
    const float* fm    = (const float*)d_in[0];
    const float* boxes = (const float*)d_in[1];
    const int*   bidx  = (const int*)d_in[2];
    float*       out   = (float*)d_out;

    box_prep_kernel<<<ROI_NBOX / 256, 256>>>(boxes, bidx, out);

    const int total = ROI_NBOX * ROI_HEIGHT * ROI_MAXW * (FM_C / 4); // 8,388,608
    roi_rotate_kernel<<<total / 256, 256>>>(fm, out);
}